// round 14
// baseline (speedup 1.0000x reference)
#include <cuda_runtime.h>
#include <math.h>

#define NUSERS 100000
#define NITEMS 50000
#define NFEATS 512
#define DIM 32
#define ESOC 3200000
#define EUI 3200000
#define NPAIRS 1000000

// ---------------- scratch ----------------
__device__ double g_red[8];            // [0,1]=uf sum/sq [2,3]=itf [4,5]=usig [6,7]=isig
__device__ float  g_colsum[DIM];
__device__ float  g_user_sig[NUSERS * DIM];
__device__ float  g_item_sig[NITEMS * DIM];
__device__ float  g_user_fus[NUSERS * DIM];
__device__ float  g_item_fus[NITEMS * DIM];
__device__ float  g_h1[NUSERS * DIM];
__device__ float  g_last[NUSERS * DIM];

// ---------------- init ----------------
__global__ void k_init() {
    int i = blockIdx.x * blockDim.x + threadIdx.x;
    float4 z = make_float4(0.f, 0.f, 0.f, 0.f);
    const int n4 = NUSERS * DIM / 4;
    if (i < n4) {
        reinterpret_cast<float4*>(g_h1)[i]   = z;
        reinterpret_cast<float4*>(g_last)[i] = z;
    }
    if (i < 8) g_red[i] = 0.0;
}

// ---------------- column sums of W ----------------
__global__ void k_colsum(const float* __restrict__ W) {
    __shared__ float s[8][DIM];
    int c = threadIdx.x & 31;
    int g = threadIdx.x >> 5;
    float acc = 0.f;
    for (int k = g; k < NFEATS; k += 8) acc += W[k * DIM + c];
    s[g][c] = acc;
    __syncthreads();
    if (g == 0) {
        float t = 0.f;
#pragma unroll
        for (int j = 0; j < 8; j++) t += s[j][c];
        g_colsum[c] = t;
    }
}

// ---------------- GEMM: 128x32 tile, 8x4 per thread, row-major sF ----------------
__global__ __launch_bounds__(128) void k_gemm(const float* __restrict__ F,
                                              const float* __restrict__ W,
                                              int M, int redIdx, int outSel) {
    __shared__ float sF[128][33];
    __shared__ float sW[32][36];
    float* __restrict__ out = outSel ? g_item_sig : g_user_sig;

    int t  = threadIdx.x;
    int tc = t & 7;        // col group (4 cols)
    int tr = t >> 3;       // row group (8 rows), 0..15
    int row0 = blockIdx.x * 128;

    float acc[8][4] = {};
    float lsum = 0.f, lsq = 0.f;

    for (int kt = 0; kt < NFEATS / 32; ++kt) {
        int k0 = kt * 32;
        // F tile: 128 rows x 32 k = 1024 float4, 8 per thread
#pragma unroll
        for (int i = 0; i < 8; ++i) {
            int fi = t + i * 128;
            int r = fi >> 3, kq = fi & 7;
            float4 v = make_float4(0.f, 0.f, 0.f, 0.f);
            int grow = row0 + r;
            if (grow < M)
                v = *reinterpret_cast<const float4*>(&F[(size_t)grow * NFEATS + k0 + kq * 4]);
            sF[r][kq * 4 + 0] = v.x; sF[r][kq * 4 + 1] = v.y;
            sF[r][kq * 4 + 2] = v.z; sF[r][kq * 4 + 3] = v.w;
            lsum += v.x + v.y + v.z + v.w;
            lsq  += v.x * v.x + v.y * v.y + v.z * v.z + v.w * v.w;
        }
        // W tile
#pragma unroll
        for (int i = 0; i < 2; ++i) {
            int fi = t + i * 128;
            int kr = fi >> 3, kq = fi & 7;
            float4 w = *reinterpret_cast<const float4*>(&W[(size_t)(k0 + kr) * DIM + kq * 4]);
            sW[kr][kq * 4 + 0] = w.x; sW[kr][kq * 4 + 1] = w.y;
            sW[kr][kq * 4 + 2] = w.z; sW[kr][kq * 4 + 3] = w.w;
        }
        __syncthreads();
#pragma unroll
        for (int k = 0; k < 32; ++k) {
            float4 w = *reinterpret_cast<float4*>(&sW[k][tc * 4]);
            float f0 = sF[tr * 8 + 0][k];
            float f1 = sF[tr * 8 + 1][k];
            float f2 = sF[tr * 8 + 2][k];
            float f3 = sF[tr * 8 + 3][k];
            float f4 = sF[tr * 8 + 4][k];
            float f5 = sF[tr * 8 + 5][k];
            float f6 = sF[tr * 8 + 6][k];
            float f7 = sF[tr * 8 + 7][k];
            acc[0][0] += f0 * w.x; acc[0][1] += f0 * w.y; acc[0][2] += f0 * w.z; acc[0][3] += f0 * w.w;
            acc[1][0] += f1 * w.x; acc[1][1] += f1 * w.y; acc[1][2] += f1 * w.z; acc[1][3] += f1 * w.w;
            acc[2][0] += f2 * w.x; acc[2][1] += f2 * w.y; acc[2][2] += f2 * w.z; acc[2][3] += f2 * w.w;
            acc[3][0] += f3 * w.x; acc[3][1] += f3 * w.y; acc[3][2] += f3 * w.z; acc[3][3] += f3 * w.w;
            acc[4][0] += f4 * w.x; acc[4][1] += f4 * w.y; acc[4][2] += f4 * w.z; acc[4][3] += f4 * w.w;
            acc[5][0] += f5 * w.x; acc[5][1] += f5 * w.y; acc[5][2] += f5 * w.z; acc[5][3] += f5 * w.w;
            acc[6][0] += f6 * w.x; acc[6][1] += f6 * w.y; acc[6][2] += f6 * w.z; acc[6][3] += f6 * w.w;
            acc[7][0] += f7 * w.x; acc[7][1] += f7 * w.y; acc[7][2] += f7 * w.z; acc[7][3] += f7 * w.w;
        }
        __syncthreads();
    }

#pragma unroll
    for (int o = 16; o; o >>= 1) {
        lsum += __shfl_down_sync(0xffffffffu, lsum, o);
        lsq  += __shfl_down_sync(0xffffffffu, lsq, o);
    }
    __shared__ double sred[4][2];
    int wid = t >> 5, lane = t & 31;
    if (lane == 0) { sred[wid][0] = (double)lsum; sred[wid][1] = (double)lsq; }
    __syncthreads();
    if (t == 0) {
        double a = 0.0, b = 0.0;
#pragma unroll
        for (int j = 0; j < 4; j++) { a += sred[j][0]; b += sred[j][1]; }
        atomicAdd(&g_red[redIdx], a);
        atomicAdd(&g_red[redIdx + 1], b);
    }

#pragma unroll
    for (int i = 0; i < 8; ++i) {
        int grow = row0 + tr * 8 + i;
        if (grow < M) {
            float4 o4 = make_float4(acc[i][0], acc[i][1], acc[i][2], acc[i][3]);
            *reinterpret_cast<float4*>(&out[(size_t)grow * DIM + tc * 4]) = o4;
        }
    }
}

// ---------------- epilogue: per-block fp64 scalar (thread 0), fp32 body ----------------
__global__ void k_epi(const float* __restrict__ b, int n, double Nfeat,
                      int si, int so, int sel) {
    float* __restrict__ sig = sel ? g_item_sig : g_user_sig;
    __shared__ float s_inv, s_mis;
    if (threadIdx.x == 0) {
        double fsum = g_red[si], fsq = g_red[si + 1];
        double mean = fsum / Nfeat;
        double var  = (fsq - fsum * fsum / Nfeat) / (Nfeat - 1.0);
        double inv  = 1.0 / sqrt(var);
        s_inv = (float)inv;
        s_mis = (float)(mean * inv);
    }
    __syncthreads();
    float inv_s = s_inv, mis = s_mis;

    int i = blockIdx.x * blockDim.x + threadIdx.x;
    float lsum = 0.f, lsq = 0.f;
    if (i < n) {
        int j = i & (DIM - 1);
        float x = sig[i] * inv_s + b[j] - mis * g_colsum[j];
        float v = 1.f / (1.f + expf(-x));
        sig[i] = v;
        lsum = v;
        lsq  = v * v;
    }
#pragma unroll
    for (int o = 16; o; o >>= 1) {
        lsum += __shfl_down_sync(0xffffffffu, lsum, o);
        lsq  += __shfl_down_sync(0xffffffffu, lsq, o);
    }
    __shared__ double sred[8][2];
    int wid = threadIdx.x >> 5, lane = threadIdx.x & 31;
    if (lane == 0) { sred[wid][0] = (double)lsum; sred[wid][1] = (double)lsq; }
    __syncthreads();
    if (threadIdx.x == 0) {
        double a = 0.0, c = 0.0;
#pragma unroll
        for (int j = 0; j < 8; j++) { a += sred[j][0]; c += sred[j][1]; }
        atomicAdd(&g_red[so], a);
        atomicAdd(&g_red[so + 1], c);
    }
}

// ---------------- fusion: per-block fp64 scalar (thread 0), fp32 body ----------------
__global__ void k_fusion(const float* __restrict__ emb, int n, double Nd,
                         int si, int sel) {
    const float* __restrict__ sig = sel ? g_item_sig : g_user_sig;
    float* __restrict__ fus = sel ? g_item_fus : g_user_fus;
    __shared__ float s_m, s_inv;
    if (threadIdx.x == 0) {
        double s0 = g_red[si], s1 = g_red[si + 1];
        double mean = s0 / Nd;
        double var  = (s1 - s0 * s0 / Nd) / (Nd - 1.0);
        s_m   = (float)mean;
        s_inv = (float)(1.0 / sqrt(var));
    }
    __syncthreads();
    float m = s_m, inv = s_inv;
    int i = blockIdx.x * blockDim.x + threadIdx.x;
    if (i < n) fus[i] = (sig[i] - m) * inv + emb[i];
}

// ---------------- SpMM: smem-staged, straight-line batch of 4 ----------------
#define SPMM_EB 1024
__global__ __launch_bounds__(256) void k_spmm(const int* __restrict__ rows,
                                              const int* __restrict__ cols,
                                              const float* __restrict__ vals,
                                              int selX, int selOut) {
    __shared__ int   sr[SPMM_EB];
    __shared__ int   sc[SPMM_EB];
    __shared__ float sv[SPMM_EB];
    const float* __restrict__ X =
        (selX == 0) ? g_item_fus : (selX == 1) ? g_user_fus : g_h1;
    float* __restrict__ OUT = selOut ? g_h1 : g_last;

    int base = blockIdx.x * SPMM_EB;
#pragma unroll
    for (int i = 0; i < 4; ++i) {
        int idx = threadIdx.x + i * 256;
        sr[idx] = rows[base + idx];
        sc[idx] = cols[base + idx];
        sv[idx] = vals[base + idx];
    }
    __syncthreads();

    int sub = threadIdx.x & 7;
    int grp = threadIdx.x >> 3;
#pragma unroll
    for (int pass = 0; pass < SPMM_EB / 128; ++pass) {
        int e = grp + pass * 128;
        int r0 = sr[e],       c0 = sc[e];       float v0 = sv[e];
        int r1 = sr[e + 32],  c1 = sc[e + 32];  float v1 = sv[e + 32];
        int r2 = sr[e + 64],  c2 = sc[e + 64];  float v2 = sv[e + 64];
        int r3 = sr[e + 96],  c3 = sc[e + 96];  float v3 = sv[e + 96];
        float4 x0 = *reinterpret_cast<const float4*>(&X[(size_t)c0 * DIM + sub * 4]);
        float4 x1 = *reinterpret_cast<const float4*>(&X[(size_t)c1 * DIM + sub * 4]);
        float4 x2 = *reinterpret_cast<const float4*>(&X[(size_t)c2 * DIM + sub * 4]);
        float4 x3 = *reinterpret_cast<const float4*>(&X[(size_t)c3 * DIM + sub * 4]);
        float* p0 = &OUT[(size_t)r0 * DIM + sub * 4];
        float* p1 = &OUT[(size_t)r1 * DIM + sub * 4];
        float* p2 = &OUT[(size_t)r2 * DIM + sub * 4];
        float* p3 = &OUT[(size_t)r3 * DIM + sub * 4];
        asm volatile("red.global.add.v4.f32 [%0], {%1,%2,%3,%4};"
                     :: "l"(p0), "f"(x0.x * v0), "f"(x0.y * v0), "f"(x0.z * v0), "f"(x0.w * v0));
        asm volatile("red.global.add.v4.f32 [%0], {%1,%2,%3,%4};"
                     :: "l"(p1), "f"(x1.x * v1), "f"(x1.y * v1), "f"(x1.z * v1), "f"(x1.w * v1));
        asm volatile("red.global.add.v4.f32 [%0], {%1,%2,%3,%4};"
                     :: "l"(p2), "f"(x2.x * v2), "f"(x2.y * v2), "f"(x2.z * v2), "f"(x2.w * v2));
        asm volatile("red.global.add.v4.f32 [%0], {%1,%2,%3,%4};"
                     :: "l"(p3), "f"(x3.x * v3), "f"(x3.y * v3), "f"(x3.z * v3), "f"(x3.w * v3));
    }
}

// ---------------- prediction ----------------
__global__ __launch_bounds__(256) void k_pred(const int* __restrict__ ui,
                                              const int* __restrict__ ii,
                                              float* __restrict__ out, int out_size) {
    __shared__ int su[512];
    __shared__ int sI[512];
    int base = blockIdx.x << 9;
    int t = threadIdx.x;
    int n = NPAIRS - base; if (n > 512) n = 512;
    for (int i = t; i < n; i += 256) { su[i] = ui[base + i]; sI[i] = ii[base + i]; }
    __syncthreads();

    int sub = t & 7, grp = t >> 3;
    if (n == 512) {
#pragma unroll
        for (int pass = 0; pass < 8; ++pass) {
            int p = grp + pass * 64;
            int u0 = su[p],      i0 = sI[p];
            int u1 = su[p + 32], i1 = sI[p + 32];
            float4 a0 = *reinterpret_cast<const float4*>(&g_last[(size_t)u0 * DIM + sub * 4]);
            float4 b0 = *reinterpret_cast<const float4*>(&g_item_fus[(size_t)i0 * DIM + sub * 4]);
            float4 a1 = *reinterpret_cast<const float4*>(&g_last[(size_t)u1 * DIM + sub * 4]);
            float4 b1 = *reinterpret_cast<const float4*>(&g_item_fus[(size_t)i1 * DIM + sub * 4]);
            float d0 = a0.x * b0.x + a0.y * b0.y + a0.z * b0.z + a0.w * b0.w;
            float d1 = a1.x * b1.x + a1.y * b1.y + a1.z * b1.z + a1.w * b1.w;
#pragma unroll
            for (int o = 4; o; o >>= 1) {
                d0 += __shfl_down_sync(0xffffffffu, d0, o, 8);
                d1 += __shfl_down_sync(0xffffffffu, d1, o, 8);
            }
            if (sub == 0) {
                int gp0 = base + p, gp1 = base + p + 32;
                out[gp0] = d0;
                out[NPAIRS + gp0] = 1.f / (1.f + expf(-d0));
                out[gp1] = d1;
                out[NPAIRS + gp1] = 1.f / (1.f + expf(-d1));
            }
        }
    } else {
        for (int p = grp; p < n; p += 32) {
            int u  = su[p];
            int it = sI[p];
            float4 a = *reinterpret_cast<const float4*>(&g_last[(size_t)u * DIM + sub * 4]);
            float4 b = *reinterpret_cast<const float4*>(&g_item_fus[(size_t)it * DIM + sub * 4]);
            float d = a.x * b.x + a.y * b.y + a.z * b.z + a.w * b.w;
#pragma unroll
            for (int o = 4; o; o >>= 1) d += __shfl_down_sync(0xffffffffu, d, o, 8);
            if (sub == 0) {
                int gp = base + p;
                if (gp < out_size) out[gp] = d;
                if (NPAIRS + gp < out_size) out[NPAIRS + gp] = 1.f / (1.f + expf(-d));
            }
        }
    }
}

// ---------------- launch: fork/join across two side streams ----------------
extern "C" void kernel_launch(void* const* d_in, const int* in_sizes, int n_in,
                              void* d_out, int out_size) {
    const float* uf    = (const float*)d_in[0];
    const float* itf   = (const float*)d_in[1];
    const float* uemb  = (const float*)d_in[2];
    const float* iemb  = (const float*)d_in[3];
    const float* wr_w  = (const float*)d_in[4];
    const float* wr_b  = (const float*)d_in[5];
    const int*   srows = (const int*)d_in[6];
    const int*   scols = (const int*)d_in[7];
    const float* svals = (const float*)d_in[8];
    const int*   urows = (const int*)d_in[9];
    const int*   ucols = (const int*)d_in[10];
    const float* uvals = (const float*)d_in[11];
    const int*   uidx  = (const int*)d_in[12];
    const int*   iidx  = (const int*)d_in[13];
    float* out = (float*)d_out;

    static cudaStream_t sA = 0, sB = 0;
    static cudaEvent_t  eFork = 0, eA = 0, eB = 0;
    if (sA == 0) {
        cudaStreamCreateWithFlags(&sA, cudaStreamNonBlocking);
        cudaStreamCreateWithFlags(&sB, cudaStreamNonBlocking);
        cudaEventCreateWithFlags(&eFork, cudaEventDisableTiming);
        cudaEventCreateWithFlags(&eA, cudaEventDisableTiming);
        cudaEventCreateWithFlags(&eB, cudaEventDisableTiming);
    }

    k_init<<<(NUSERS * DIM / 4 + 255) / 256, 256>>>();
    k_colsum<<<1, 256>>>(wr_w);
    cudaEventRecord(eFork, 0);
    cudaStreamWaitEvent(sA, eFork, 0);
    cudaStreamWaitEvent(sB, eFork, 0);

    // stream A: item chain -> UI SpMM
    k_gemm<<<(NITEMS + 127) / 128, 128, 0, sA>>>(itf, wr_w, NITEMS, 2, 1);
    k_epi<<<(NITEMS * DIM + 255) / 256, 256, 0, sA>>>(wr_b, NITEMS * DIM,
                                                      (double)NITEMS * NFEATS, 2, 6, 1);
    k_fusion<<<(NITEMS * DIM + 255) / 256, 256, 0, sA>>>(iemb, NITEMS * DIM,
                                                         (double)(NITEMS * DIM), 6, 1);
    k_spmm<<<EUI / SPMM_EB, 256, 0, sA>>>(urows, ucols, uvals, 0, 0);

    // stream B: user chain -> soc1 -> soc2
    k_gemm<<<(NUSERS + 127) / 128, 128, 0, sB>>>(uf, wr_w, NUSERS, 0, 0);
    k_epi<<<(NUSERS * DIM + 255) / 256, 256, 0, sB>>>(wr_b, NUSERS * DIM,
                                                      (double)NUSERS * NFEATS, 0, 4, 0);
    k_fusion<<<(NUSERS * DIM + 255) / 256, 256, 0, sB>>>(uemb, NUSERS * DIM,
                                                         (double)(NUSERS * DIM), 4, 0);
    k_spmm<<<ESOC / SPMM_EB, 256, 0, sB>>>(srows, scols, svals, 1, 1);
    k_spmm<<<ESOC / SPMM_EB, 256, 0, sB>>>(srows, scols, svals, 2, 0);

    // join
    cudaEventRecord(eA, sA);
    cudaEventRecord(eB, sB);
    cudaStreamWaitEvent(0, eA, 0);
    cudaStreamWaitEvent(0, eB, 0);
    k_pred<<<(NPAIRS + 511) / 512, 256>>>(uidx, iidx, out, out_size);
}

// round 15
// speedup vs baseline: 1.1424x; 1.1424x over previous
#include <cuda_runtime.h>
#include <math.h>

#define NUSERS 100000
#define NITEMS 50000
#define NFEATS 512
#define DIM 32
#define ESOC 3200000
#define EUI 3200000
#define NPAIRS 1000000

// ---------------- scratch ----------------
__device__ double g_red[8];            // [0,1]=uf sum/sq [2,3]=itf [4,5]=usig [6,7]=isig
__device__ float  g_scal[8];
__device__ float  g_colsum[DIM];
__device__ float  g_user_sig[NUSERS * DIM];
__device__ float  g_item_sig[NITEMS * DIM];
__device__ float  g_user_fus[NUSERS * DIM];
__device__ float  g_item_fus[NITEMS * DIM];
__device__ float  g_h1[NUSERS * DIM];
__device__ float  g_last[NUSERS * DIM];

// ---------------- init ----------------
__global__ void k_init() {
    int i = blockIdx.x * blockDim.x + threadIdx.x;
    float4 z = make_float4(0.f, 0.f, 0.f, 0.f);
    const int n4 = NUSERS * DIM / 4;
    if (i < n4) {
        reinterpret_cast<float4*>(g_h1)[i]   = z;
        reinterpret_cast<float4*>(g_last)[i] = z;
    }
    if (i < 8) g_red[i] = 0.0;
}

// ---------------- column sums of W ----------------
__global__ void k_colsum(const float* __restrict__ W) {
    __shared__ float s[8][DIM];
    int c = threadIdx.x & 31;
    int g = threadIdx.x >> 5;
    float acc = 0.f;
    for (int k = g; k < NFEATS; k += 8) acc += W[k * DIM + c];
    s[g][c] = acc;
    __syncthreads();
    if (g == 0) {
        float t = 0.f;
#pragma unroll
        for (int j = 0; j < 8; j++) t += s[j][c];
        g_colsum[c] = t;
    }
}

// ---------------- scalar stats: fp64 ONCE ----------------
__global__ void k_scal(int si, double N, int mode) {
    double s0 = g_red[si], s1 = g_red[si + 1];
    double mean = s0 / N;
    double var  = (s1 - s0 * s0 / N) / (N - 1.0);
    double inv  = 1.0 / sqrt(var);
    if (mode == 0) {
        g_scal[si]     = (float)inv;
        g_scal[si + 1] = (float)(mean * inv);
    } else {
        g_scal[si]     = (float)mean;
        g_scal[si + 1] = (float)inv;
    }
}

// ---------------- GEMM: 128x32 tile, 8x4 per thread, row-major sF ----------------
__global__ __launch_bounds__(128) void k_gemm(const float* __restrict__ F,
                                              const float* __restrict__ W,
                                              int M, int redIdx, int outSel) {
    __shared__ float sF[128][33];
    __shared__ float sW[32][36];
    float* __restrict__ out = outSel ? g_item_sig : g_user_sig;

    int t  = threadIdx.x;
    int tc = t & 7;
    int tr = t >> 3;
    int row0 = blockIdx.x * 128;

    float acc[8][4] = {};
    float lsum = 0.f, lsq = 0.f;

    for (int kt = 0; kt < NFEATS / 32; ++kt) {
        int k0 = kt * 32;
#pragma unroll
        for (int i = 0; i < 8; ++i) {
            int fi = t + i * 128;
            int r = fi >> 3, kq = fi & 7;
            float4 v = make_float4(0.f, 0.f, 0.f, 0.f);
            int grow = row0 + r;
            if (grow < M)
                v = *reinterpret_cast<const float4*>(&F[(size_t)grow * NFEATS + k0 + kq * 4]);
            sF[r][kq * 4 + 0] = v.x; sF[r][kq * 4 + 1] = v.y;
            sF[r][kq * 4 + 2] = v.z; sF[r][kq * 4 + 3] = v.w;
            lsum += v.x + v.y + v.z + v.w;
            lsq  += v.x * v.x + v.y * v.y + v.z * v.z + v.w * v.w;
        }
#pragma unroll
        for (int i = 0; i < 2; ++i) {
            int fi = t + i * 128;
            int kr = fi >> 3, kq = fi & 7;
            float4 w = *reinterpret_cast<const float4*>(&W[(size_t)(k0 + kr) * DIM + kq * 4]);
            sW[kr][kq * 4 + 0] = w.x; sW[kr][kq * 4 + 1] = w.y;
            sW[kr][kq * 4 + 2] = w.z; sW[kr][kq * 4 + 3] = w.w;
        }
        __syncthreads();
#pragma unroll
        for (int k = 0; k < 32; ++k) {
            float4 w = *reinterpret_cast<float4*>(&sW[k][tc * 4]);
            float f0 = sF[tr * 8 + 0][k];
            float f1 = sF[tr * 8 + 1][k];
            float f2 = sF[tr * 8 + 2][k];
            float f3 = sF[tr * 8 + 3][k];
            float f4 = sF[tr * 8 + 4][k];
            float f5 = sF[tr * 8 + 5][k];
            float f6 = sF[tr * 8 + 6][k];
            float f7 = sF[tr * 8 + 7][k];
            acc[0][0] += f0 * w.x; acc[0][1] += f0 * w.y; acc[0][2] += f0 * w.z; acc[0][3] += f0 * w.w;
            acc[1][0] += f1 * w.x; acc[1][1] += f1 * w.y; acc[1][2] += f1 * w.z; acc[1][3] += f1 * w.w;
            acc[2][0] += f2 * w.x; acc[2][1] += f2 * w.y; acc[2][2] += f2 * w.z; acc[2][3] += f2 * w.w;
            acc[3][0] += f3 * w.x; acc[3][1] += f3 * w.y; acc[3][2] += f3 * w.z; acc[3][3] += f3 * w.w;
            acc[4][0] += f4 * w.x; acc[4][1] += f4 * w.y; acc[4][2] += f4 * w.z; acc[4][3] += f4 * w.w;
            acc[5][0] += f5 * w.x; acc[5][1] += f5 * w.y; acc[5][2] += f5 * w.z; acc[5][3] += f5 * w.w;
            acc[6][0] += f6 * w.x; acc[6][1] += f6 * w.y; acc[6][2] += f6 * w.z; acc[6][3] += f6 * w.w;
            acc[7][0] += f7 * w.x; acc[7][1] += f7 * w.y; acc[7][2] += f7 * w.z; acc[7][3] += f7 * w.w;
        }
        __syncthreads();
    }

#pragma unroll
    for (int o = 16; o; o >>= 1) {
        lsum += __shfl_down_sync(0xffffffffu, lsum, o);
        lsq  += __shfl_down_sync(0xffffffffu, lsq, o);
    }
    __shared__ double sred[4][2];
    int wid = t >> 5, lane = t & 31;
    if (lane == 0) { sred[wid][0] = (double)lsum; sred[wid][1] = (double)lsq; }
    __syncthreads();
    if (t == 0) {
        double a = 0.0, b = 0.0;
#pragma unroll
        for (int j = 0; j < 4; j++) { a += sred[j][0]; b += sred[j][1]; }
        atomicAdd(&g_red[redIdx], a);
        atomicAdd(&g_red[redIdx + 1], b);
    }

#pragma unroll
    for (int i = 0; i < 8; ++i) {
        int grow = row0 + tr * 8 + i;
        if (grow < M) {
            float4 o4 = make_float4(acc[i][0], acc[i][1], acc[i][2], acc[i][3]);
            *reinterpret_cast<float4*>(&out[(size_t)grow * DIM + tc * 4]) = o4;
        }
    }
}

// ---------------- epilogue: pure fp32, scalars preloaded ----------------
__global__ void k_epi(const float* __restrict__ b, int n, int si, int so, int sel) {
    float* __restrict__ sig = sel ? g_item_sig : g_user_sig;
    float inv_s = g_scal[si];
    float mis   = g_scal[si + 1];

    int i = blockIdx.x * blockDim.x + threadIdx.x;
    float lsum = 0.f, lsq = 0.f;
    if (i < n) {
        int j = i & (DIM - 1);
        float x = sig[i] * inv_s + b[j] - mis * g_colsum[j];
        float v = 1.f / (1.f + expf(-x));
        sig[i] = v;
        lsum = v;
        lsq  = v * v;
    }
#pragma unroll
    for (int o = 16; o; o >>= 1) {
        lsum += __shfl_down_sync(0xffffffffu, lsum, o);
        lsq  += __shfl_down_sync(0xffffffffu, lsq, o);
    }
    __shared__ double sred[8][2];
    int wid = threadIdx.x >> 5, lane = threadIdx.x & 31;
    if (lane == 0) { sred[wid][0] = (double)lsum; sred[wid][1] = (double)lsq; }
    __syncthreads();
    if (threadIdx.x == 0) {
        double a = 0.0, c = 0.0;
#pragma unroll
        for (int j = 0; j < 8; j++) { a += sred[j][0]; c += sred[j][1]; }
        atomicAdd(&g_red[so], a);
        atomicAdd(&g_red[so + 1], c);
    }
}

// ---------------- fusion: pure fp32, scalars preloaded ----------------
__global__ void k_fusion(const float* __restrict__ emb, int n, int si, int sel) {
    const float* __restrict__ sig = sel ? g_item_sig : g_user_sig;
    float* __restrict__ fus = sel ? g_item_fus : g_user_fus;
    float m   = g_scal[si];
    float inv = g_scal[si + 1];
    int i = blockIdx.x * blockDim.x + threadIdx.x;
    if (i < n) fus[i] = (sig[i] - m) * inv + emb[i];
}

// ---------------- SpMM: smem-staged, straight-line batch of 4 ----------------
#define SPMM_EB 1024
__global__ __launch_bounds__(256) void k_spmm(const int* __restrict__ rows,
                                              const int* __restrict__ cols,
                                              const float* __restrict__ vals,
                                              int selX, int selOut) {
    __shared__ int   sr[SPMM_EB];
    __shared__ int   sc[SPMM_EB];
    __shared__ float sv[SPMM_EB];
    const float* __restrict__ X =
        (selX == 0) ? g_item_fus : (selX == 1) ? g_user_fus : g_h1;
    float* __restrict__ OUT = selOut ? g_h1 : g_last;

    int base = blockIdx.x * SPMM_EB;
#pragma unroll
    for (int i = 0; i < 4; ++i) {
        int idx = threadIdx.x + i * 256;
        sr[idx] = rows[base + idx];
        sc[idx] = cols[base + idx];
        sv[idx] = vals[base + idx];
    }
    __syncthreads();

    int sub = threadIdx.x & 7;
    int grp = threadIdx.x >> 3;
#pragma unroll
    for (int pass = 0; pass < SPMM_EB / 128; ++pass) {
        int e = grp + pass * 128;
        int r0 = sr[e],       c0 = sc[e];       float v0 = sv[e];
        int r1 = sr[e + 32],  c1 = sc[e + 32];  float v1 = sv[e + 32];
        int r2 = sr[e + 64],  c2 = sc[e + 64];  float v2 = sv[e + 64];
        int r3 = sr[e + 96],  c3 = sc[e + 96];  float v3 = sv[e + 96];
        float4 x0 = *reinterpret_cast<const float4*>(&X[(size_t)c0 * DIM + sub * 4]);
        float4 x1 = *reinterpret_cast<const float4*>(&X[(size_t)c1 * DIM + sub * 4]);
        float4 x2 = *reinterpret_cast<const float4*>(&X[(size_t)c2 * DIM + sub * 4]);
        float4 x3 = *reinterpret_cast<const float4*>(&X[(size_t)c3 * DIM + sub * 4]);
        float* p0 = &OUT[(size_t)r0 * DIM + sub * 4];
        float* p1 = &OUT[(size_t)r1 * DIM + sub * 4];
        float* p2 = &OUT[(size_t)r2 * DIM + sub * 4];
        float* p3 = &OUT[(size_t)r3 * DIM + sub * 4];
        asm volatile("red.global.add.v4.f32 [%0], {%1,%2,%3,%4};"
                     :: "l"(p0), "f"(x0.x * v0), "f"(x0.y * v0), "f"(x0.z * v0), "f"(x0.w * v0));
        asm volatile("red.global.add.v4.f32 [%0], {%1,%2,%3,%4};"
                     :: "l"(p1), "f"(x1.x * v1), "f"(x1.y * v1), "f"(x1.z * v1), "f"(x1.w * v1));
        asm volatile("red.global.add.v4.f32 [%0], {%1,%2,%3,%4};"
                     :: "l"(p2), "f"(x2.x * v2), "f"(x2.y * v2), "f"(x2.z * v2), "f"(x2.w * v2));
        asm volatile("red.global.add.v4.f32 [%0], {%1,%2,%3,%4};"
                     :: "l"(p3), "f"(x3.x * v3), "f"(x3.y * v3), "f"(x3.z * v3), "f"(x3.w * v3));
    }
}

// ---------------- prediction ----------------
__global__ __launch_bounds__(256) void k_pred(const int* __restrict__ ui,
                                              const int* __restrict__ ii,
                                              float* __restrict__ out, int out_size) {
    __shared__ int su[512];
    __shared__ int sI[512];
    int base = blockIdx.x << 9;
    int t = threadIdx.x;
    int n = NPAIRS - base; if (n > 512) n = 512;
    for (int i = t; i < n; i += 256) { su[i] = ui[base + i]; sI[i] = ii[base + i]; }
    __syncthreads();

    int sub = t & 7, grp = t >> 3;
    if (n == 512) {
#pragma unroll
        for (int pass = 0; pass < 8; ++pass) {
            int p = grp + pass * 64;
            int u0 = su[p],      i0 = sI[p];
            int u1 = su[p + 32], i1 = sI[p + 32];
            float4 a0 = *reinterpret_cast<const float4*>(&g_last[(size_t)u0 * DIM + sub * 4]);
            float4 b0 = *reinterpret_cast<const float4*>(&g_item_fus[(size_t)i0 * DIM + sub * 4]);
            float4 a1 = *reinterpret_cast<const float4*>(&g_last[(size_t)u1 * DIM + sub * 4]);
            float4 b1 = *reinterpret_cast<const float4*>(&g_item_fus[(size_t)i1 * DIM + sub * 4]);
            float d0 = a0.x * b0.x + a0.y * b0.y + a0.z * b0.z + a0.w * b0.w;
            float d1 = a1.x * b1.x + a1.y * b1.y + a1.z * b1.z + a1.w * b1.w;
#pragma unroll
            for (int o = 4; o; o >>= 1) {
                d0 += __shfl_down_sync(0xffffffffu, d0, o, 8);
                d1 += __shfl_down_sync(0xffffffffu, d1, o, 8);
            }
            if (sub == 0) {
                int gp0 = base + p, gp1 = base + p + 32;
                out[gp0] = d0;
                out[NPAIRS + gp0] = 1.f / (1.f + expf(-d0));
                out[gp1] = d1;
                out[NPAIRS + gp1] = 1.f / (1.f + expf(-d1));
            }
        }
    } else {
        for (int p = grp; p < n; p += 32) {
            int u  = su[p];
            int it = sI[p];
            float4 a = *reinterpret_cast<const float4*>(&g_last[(size_t)u * DIM + sub * 4]);
            float4 b = *reinterpret_cast<const float4*>(&g_item_fus[(size_t)it * DIM + sub * 4]);
            float d = a.x * b.x + a.y * b.y + a.z * b.z + a.w * b.w;
#pragma unroll
            for (int o = 4; o; o >>= 1) d += __shfl_down_sync(0xffffffffu, d, o, 8);
            if (sub == 0) {
                int gp = base + p;
                if (gp < out_size) out[gp] = d;
                if (NPAIRS + gp < out_size) out[NPAIRS + gp] = 1.f / (1.f + expf(-d));
            }
        }
    }
}

// ---------------- launch: fork immediately; init/colsum on slack stream ----------------
extern "C" void kernel_launch(void* const* d_in, const int* in_sizes, int n_in,
                              void* d_out, int out_size) {
    const float* uf    = (const float*)d_in[0];
    const float* itf   = (const float*)d_in[1];
    const float* uemb  = (const float*)d_in[2];
    const float* iemb  = (const float*)d_in[3];
    const float* wr_w  = (const float*)d_in[4];
    const float* wr_b  = (const float*)d_in[5];
    const int*   srows = (const int*)d_in[6];
    const int*   scols = (const int*)d_in[7];
    const float* svals = (const float*)d_in[8];
    const int*   urows = (const int*)d_in[9];
    const int*   ucols = (const int*)d_in[10];
    const float* uvals = (const float*)d_in[11];
    const int*   uidx  = (const int*)d_in[12];
    const int*   iidx  = (const int*)d_in[13];
    float* out = (float*)d_out;

    static cudaStream_t sA = 0, sB = 0;
    static cudaEvent_t  eFork = 0, eInit = 0, eA = 0, eB = 0;
    if (sA == 0) {
        cudaStreamCreateWithFlags(&sA, cudaStreamNonBlocking);
        cudaStreamCreateWithFlags(&sB, cudaStreamNonBlocking);
        cudaEventCreateWithFlags(&eFork, cudaEventDisableTiming);
        cudaEventCreateWithFlags(&eInit, cudaEventDisableTiming);
        cudaEventCreateWithFlags(&eA, cudaEventDisableTiming);
        cudaEventCreateWithFlags(&eB, cudaEventDisableTiming);
    }

    cudaEventRecord(eFork, 0);
    cudaStreamWaitEvent(sA, eFork, 0);
    cudaStreamWaitEvent(sB, eFork, 0);

    // stream A (slack): init + colsum, then item chain -> UI SpMM
    k_init<<<(NUSERS * DIM / 4 + 255) / 256, 256, 0, sA>>>();
    k_colsum<<<1, 256, 0, sA>>>(wr_w);
    cudaEventRecord(eInit, sA);                 // init + colsum done
    k_gemm<<<(NITEMS + 127) / 128, 128, 0, sA>>>(itf, wr_w, NITEMS, 2, 1);
    k_scal<<<1, 1, 0, sA>>>(2, (double)NITEMS * NFEATS, 0);
    k_epi<<<(NITEMS * DIM + 255) / 256, 256, 0, sA>>>(wr_b, NITEMS * DIM, 2, 6, 1);
    k_scal<<<1, 1, 0, sA>>>(6, (double)(NITEMS * DIM), 1);
    k_fusion<<<(NITEMS * DIM + 255) / 256, 256, 0, sA>>>(iemb, NITEMS * DIM, 6, 1);
    k_spmm<<<EUI / SPMM_EB, 256, 0, sA>>>(urows, ucols, uvals, 0, 0);

    // stream B (critical): user GEMM starts at t=0
    k_gemm<<<(NUSERS + 127) / 128, 128, 0, sB>>>(uf, wr_w, NUSERS, 0, 0);
    k_scal<<<1, 1, 0, sB>>>(0, (double)NUSERS * NFEATS, 0);
    cudaStreamWaitEvent(sB, eInit, 0);          // need colsum (epi) + zeroed bufs (spmm)
    k_epi<<<(NUSERS * DIM + 255) / 256, 256, 0, sB>>>(wr_b, NUSERS * DIM, 0, 4, 0);
    k_scal<<<1, 1, 0, sB>>>(4, (double)(NUSERS * DIM), 1);
    k_fusion<<<(NUSERS * DIM + 255) / 256, 256, 0, sB>>>(uemb, NUSERS * DIM, 4, 0);
    k_spmm<<<ESOC / SPMM_EB, 256, 0, sB>>>(srows, scols, svals, 1, 1);
    k_spmm<<<ESOC / SPMM_EB, 256, 0, sB>>>(srows, scols, svals, 2, 0);

    // join
    cudaEventRecord(eA, sA);
    cudaEventRecord(eB, sB);
    cudaStreamWaitEvent(0, eA, 0);
    cudaStreamWaitEvent(0, eB, 0);
    k_pred<<<(NPAIRS + 511) / 512, 256>>>(uidx, iidx, out, out_size);
}

// round 17
// speedup vs baseline: 1.1865x; 1.0386x over previous
#include <cuda_runtime.h>
#include <math.h>
#include <stdint.h>

#define NUSERS 100000
#define NITEMS 50000
#define NFEATS 512
#define DIM 32
#define ESOC 3200000
#define EUI 3200000
#define NPAIRS 1000000

// ---------------- scratch ----------------
__device__ double   g_red[8];          // [0,1]=uf sum/sq [2,3]=itf [4,5]=usig [6,7]=isig
__device__ float    g_scal[8];
__device__ float    g_colsum[DIM];
__device__ uint32_t g_Wbig[NFEATS * DIM];    // tf32 bit patterns
__device__ uint32_t g_Wsmall[NFEATS * DIM];
__device__ float    g_user_sig[NUSERS * DIM];
__device__ float    g_item_sig[NITEMS * DIM];
__device__ float    g_user_fus[NUSERS * DIM];
__device__ float    g_item_fus[NITEMS * DIM];
__device__ float    g_h1[NUSERS * DIM];
__device__ float    g_last[NUSERS * DIM];

// ---------------- init ----------------
__global__ void k_init() {
    int i = blockIdx.x * blockDim.x + threadIdx.x;
    float4 z = make_float4(0.f, 0.f, 0.f, 0.f);
    const int n4 = NUSERS * DIM / 4;
    if (i < n4) {
        reinterpret_cast<float4*>(g_h1)[i]   = z;
        reinterpret_cast<float4*>(g_last)[i] = z;
    }
    if (i < 8) g_red[i] = 0.0;
}

// ---------------- W split: fp32 -> tf32 big + small (once) ----------------
__global__ void k_wsplit(const float* __restrict__ W) {
    int i = blockIdx.x * blockDim.x + threadIdx.x;
    if (i < NFEATS * DIM) {
        float w = W[i];
        uint32_t big;
        asm("cvt.rna.tf32.f32 %0, %1;" : "=r"(big) : "f"(w));
        float rem = w - __uint_as_float(big);
        uint32_t small;
        asm("cvt.rna.tf32.f32 %0, %1;" : "=r"(small) : "f"(rem));
        g_Wbig[i] = big;
        g_Wsmall[i] = small;
    }
}

// ---------------- column sums of W ----------------
__global__ void k_colsum(const float* __restrict__ W) {
    __shared__ float s[8][DIM];
    int c = threadIdx.x & 31;
    int g = threadIdx.x >> 5;
    float acc = 0.f;
    for (int k = g; k < NFEATS; k += 8) acc += W[k * DIM + c];
    s[g][c] = acc;
    __syncthreads();
    if (g == 0) {
        float t = 0.f;
#pragma unroll
        for (int j = 0; j < 8; j++) t += s[j][c];
        g_colsum[c] = t;
    }
}

// ---------------- scalar stats: fp64 ONCE ----------------
__global__ void k_scal(int si, double N, int mode) {
    double s0 = g_red[si], s1 = g_red[si + 1];
    double mean = s0 / N;
    double var  = (s1 - s0 * s0 / N) / (N - 1.0);
    double inv  = 1.0 / sqrt(var);
    if (mode == 0) {
        g_scal[si]     = (float)inv;
        g_scal[si + 1] = (float)(mean * inv);
    } else {
        g_scal[si]     = (float)mean;
        g_scal[si + 1] = (float)inv;
    }
}

// ---------------- helpers ----------------
__device__ __forceinline__ void tf32_split(float x, uint32_t& big, uint32_t& small) {
    asm("cvt.rna.tf32.f32 %0, %1;" : "=r"(big) : "f"(x));
    float rem = x - __uint_as_float(big);
    asm("cvt.rna.tf32.f32 %0, %1;" : "=r"(small) : "f"(rem));
}

__device__ __forceinline__ void mma_tf32(float* d,
                                         uint32_t a0, uint32_t a1, uint32_t a2, uint32_t a3,
                                         uint32_t b0, uint32_t b1) {
    asm volatile("mma.sync.aligned.m16n8k8.row.col.f32.tf32.tf32.f32 "
                 "{%0,%1,%2,%3}, {%4,%5,%6,%7}, {%8,%9}, {%0,%1,%2,%3};"
                 : "+f"(d[0]), "+f"(d[1]), "+f"(d[2]), "+f"(d[3])
                 : "r"(a0), "r"(a1), "r"(a2), "r"(a3), "r"(b0), "r"(b1));
}

// ---------------- GEMM: tensor-core 3xTF32, 64x32 tile, fused stats ----------------
// Per block: 4 warps; warp w handles rows [w*16, w*16+16). K chunked by 64 (W in smem).
// Contraction-index remap: fragment c<4 -> orig k = s*8 + 2c; c>=4 -> k = s*8 + 2(c-4)+1.
// So A (row-major, float2 at col s*8+2*tig) pairs with W rows s*8+2*tig, s*8+2*tig+1.
__global__ __launch_bounds__(128, 6) void k_gemm_tc(const float* __restrict__ F,
                                                    int M, int redIdx, int outSel) {
    __shared__ uint32_t sWb[64][36];   // pad 36: B-load bank = 8*tig+g+8j, all distinct
    __shared__ uint32_t sWs[64][36];
    float* __restrict__ out = outSel ? g_item_sig : g_user_sig;

    int t = threadIdx.x;
    int warp = t >> 5, lane = t & 31;
    int g = lane >> 2, tig = lane & 3;
    int row0 = blockIdx.x * 64;
    int rA = row0 + warp * 16 + g;       // rows for a0/a2 (c0/c1)
    int rB = rA + 8;                     // rows for a1/a3 (c2/c3)
    bool okA = rA < M, okB = rB < M;
    const float* pA = F + (size_t)rA * NFEATS;
    const float* pB = F + (size_t)rB * NFEATS;

    float acc[4][4] = {};                // [n-tile j][c0..c3]
    float lsum = 0.f, lsq = 0.f;

    for (int kc = 0; kc < NFEATS / 64; ++kc) {
        int k0 = kc * 64;
        __syncthreads();                 // previous chunk fully consumed
#pragma unroll
        for (int i = 0; i < 4; ++i) {
            int fi = t + i * 128;        // 0..511
            int kr = fi >> 3;            // 0..63
            int nq = fi & 7;             // col quad
            uint4 vb = *reinterpret_cast<const uint4*>(&g_Wbig[(size_t)(k0 + kr) * DIM + nq * 4]);
            uint4 vs = *reinterpret_cast<const uint4*>(&g_Wsmall[(size_t)(k0 + kr) * DIM + nq * 4]);
            sWb[kr][nq * 4 + 0] = vb.x; sWb[kr][nq * 4 + 1] = vb.y;
            sWb[kr][nq * 4 + 2] = vb.z; sWb[kr][nq * 4 + 3] = vb.w;
            sWs[kr][nq * 4 + 0] = vs.x; sWs[kr][nq * 4 + 1] = vs.y;
            sWs[kr][nq * 4 + 2] = vs.z; sWs[kr][nq * 4 + 3] = vs.w;
        }
        __syncthreads();
#pragma unroll
        for (int s = 0; s < 8; ++s) {
            int kk = k0 + s * 8 + 2 * tig;
            float2 a01 = okA ? *reinterpret_cast<const float2*>(pA + kk) : make_float2(0.f, 0.f);
            float2 a23 = okB ? *reinterpret_cast<const float2*>(pB + kk) : make_float2(0.f, 0.f);
            lsum += a01.x + a01.y + a23.x + a23.y;
            lsq  += a01.x * a01.x + a01.y * a01.y + a23.x * a23.x + a23.y * a23.y;

            uint32_t ab0, ab1, ab2, ab3, as0, as1, as2, as3;
            tf32_split(a01.x, ab0, as0);   // a0: row g,  c=tig   -> k = s8+2tig
            tf32_split(a23.x, ab1, as1);   // a1: row g+8, c=tig
            tf32_split(a01.y, ab2, as2);   // a2: row g,  c=tig+4 -> k = s8+2tig+1
            tf32_split(a23.y, ab3, as3);   // a3: row g+8, c=tig+4
            int wr0 = s * 8 + 2 * tig;
#pragma unroll
            for (int j = 0; j < 4; ++j) {
                int n = j * 8 + g;
                uint32_t bb0 = sWb[wr0][n];
                uint32_t bb1 = sWb[wr0 + 1][n];
                uint32_t bs0 = sWs[wr0][n];
                uint32_t bs1 = sWs[wr0 + 1][n];
                mma_tf32(acc[j], ab0, ab1, ab2, ab3, bb0, bb1);
                mma_tf32(acc[j], as0, as1, as2, as3, bb0, bb1);
                mma_tf32(acc[j], ab0, ab1, ab2, ab3, bs0, bs1);
            }
        }
    }

    // stats reduction
#pragma unroll
    for (int o = 16; o; o >>= 1) {
        lsum += __shfl_down_sync(0xffffffffu, lsum, o);
        lsq  += __shfl_down_sync(0xffffffffu, lsq, o);
    }
    __shared__ double sred[4][2];
    if (lane == 0) { sred[warp][0] = (double)lsum; sred[warp][1] = (double)lsq; }
    __syncthreads();
    if (t == 0) {
        double a = 0.0, b = 0.0;
#pragma unroll
        for (int j = 0; j < 4; j++) { a += sred[j][0]; b += sred[j][1]; }
        atomicAdd(&g_red[redIdx], a);
        atomicAdd(&g_red[redIdx + 1], b);
    }

    // store C: c0,c1 -> row rA cols j8+2tig..+1 ; c2,c3 -> row rB
#pragma unroll
    for (int j = 0; j < 4; ++j) {
        int col = j * 8 + 2 * tig;
        if (okA)
            *reinterpret_cast<float2*>(&out[(size_t)rA * DIM + col]) = make_float2(acc[j][0], acc[j][1]);
        if (okB)
            *reinterpret_cast<float2*>(&out[(size_t)rB * DIM + col]) = make_float2(acc[j][2], acc[j][3]);
    }
}

// ---------------- epilogue: pure fp32, scalars preloaded ----------------
__global__ void k_epi(const float* __restrict__ b, int n, int si, int so, int sel) {
    float* __restrict__ sig = sel ? g_item_sig : g_user_sig;
    float inv_s = g_scal[si];
    float mis   = g_scal[si + 1];

    int i = blockIdx.x * blockDim.x + threadIdx.x;
    float lsum = 0.f, lsq = 0.f;
    if (i < n) {
        int j = i & (DIM - 1);
        float x = sig[i] * inv_s + b[j] - mis * g_colsum[j];
        float v = 1.f / (1.f + expf(-x));
        sig[i] = v;
        lsum = v;
        lsq  = v * v;
    }
#pragma unroll
    for (int o = 16; o; o >>= 1) {
        lsum += __shfl_down_sync(0xffffffffu, lsum, o);
        lsq  += __shfl_down_sync(0xffffffffu, lsq, o);
    }
    __shared__ double sred[8][2];
    int wid = threadIdx.x >> 5, lane = threadIdx.x & 31;
    if (lane == 0) { sred[wid][0] = (double)lsum; sred[wid][1] = (double)lsq; }
    __syncthreads();
    if (threadIdx.x == 0) {
        double a = 0.0, c = 0.0;
#pragma unroll
        for (int j = 0; j < 8; j++) { a += sred[j][0]; c += sred[j][1]; }
        atomicAdd(&g_red[so], a);
        atomicAdd(&g_red[so + 1], c);
    }
}

// ---------------- fusion: pure fp32, scalars preloaded ----------------
__global__ void k_fusion(const float* __restrict__ emb, int n, int si, int sel) {
    const float* __restrict__ sig = sel ? g_item_sig : g_user_sig;
    float* __restrict__ fus = sel ? g_item_fus : g_user_fus;
    float m   = g_scal[si];
    float inv = g_scal[si + 1];
    int i = blockIdx.x * blockDim.x + threadIdx.x;
    if (i < n) fus[i] = (sig[i] - m) * inv + emb[i];
}

// ---------------- SpMM: smem-staged, straight-line batch of 4 ----------------
#define SPMM_EB 1024
__global__ __launch_bounds__(256) void k_spmm(const int* __restrict__ rows,
                                              const int* __restrict__ cols,
                                              const float* __restrict__ vals,
                                              int selX, int selOut) {
    __shared__ int   sr[SPMM_EB];
    __shared__ int   sc[SPMM_EB];
    __shared__ float sv[SPMM_EB];
    const float* __restrict__ X =
        (selX == 0) ? g_item_fus : (selX == 1) ? g_user_fus : g_h1;
    float* __restrict__ OUT = selOut ? g_h1 : g_last;

    int base = blockIdx.x * SPMM_EB;
#pragma unroll
    for (int i = 0; i < 4; ++i) {
        int idx = threadIdx.x + i * 256;
        sr[idx] = rows[base + idx];
        sc[idx] = cols[base + idx];
        sv[idx] = vals[base + idx];
    }
    __syncthreads();

    int sub = threadIdx.x & 7;
    int grp = threadIdx.x >> 3;
#pragma unroll
    for (int pass = 0; pass < SPMM_EB / 128; ++pass) {
        int e = grp + pass * 128;
        int r0 = sr[e],       c0 = sc[e];       float v0 = sv[e];
        int r1 = sr[e + 32],  c1 = sc[e + 32];  float v1 = sv[e + 32];
        int r2 = sr[e + 64],  c2 = sc[e + 64];  float v2 = sv[e + 64];
        int r3 = sr[e + 96],  c3 = sc[e + 96];  float v3 = sv[e + 96];
        float4 x0 = *reinterpret_cast<const float4*>(&X[(size_t)c0 * DIM + sub * 4]);
        float4 x1 = *reinterpret_cast<const float4*>(&X[(size_t)c1 * DIM + sub * 4]);
        float4 x2 = *reinterpret_cast<const float4*>(&X[(size_t)c2 * DIM + sub * 4]);
        float4 x3 = *reinterpret_cast<const float4*>(&X[(size_t)c3 * DIM + sub * 4]);
        float* p0 = &OUT[(size_t)r0 * DIM + sub * 4];
        float* p1 = &OUT[(size_t)r1 * DIM + sub * 4];
        float* p2 = &OUT[(size_t)r2 * DIM + sub * 4];
        float* p3 = &OUT[(size_t)r3 * DIM + sub * 4];
        asm volatile("red.global.add.v4.f32 [%0], {%1,%2,%3,%4};"
                     :: "l"(p0), "f"(x0.x * v0), "f"(x0.y * v0), "f"(x0.z * v0), "f"(x0.w * v0));
        asm volatile("red.global.add.v4.f32 [%0], {%1,%2,%3,%4};"
                     :: "l"(p1), "f"(x1.x * v1), "f"(x1.y * v1), "f"(x1.z * v1), "f"(x1.w * v1));
        asm volatile("red.global.add.v4.f32 [%0], {%1,%2,%3,%4};"
                     :: "l"(p2), "f"(x2.x * v2), "f"(x2.y * v2), "f"(x2.z * v2), "f"(x2.w * v2));
        asm volatile("red.global.add.v4.f32 [%0], {%1,%2,%3,%4};"
                     :: "l"(p3), "f"(x3.x * v3), "f"(x3.y * v3), "f"(x3.z * v3), "f"(x3.w * v3));
    }
}

// ---------------- prediction ----------------
__global__ __launch_bounds__(256) void k_pred(const int* __restrict__ ui,
                                              const int* __restrict__ ii,
                                              float* __restrict__ out, int out_size) {
    __shared__ int su[512];
    __shared__ int sI[512];
    int base = blockIdx.x << 9;
    int t = threadIdx.x;
    int n = NPAIRS - base; if (n > 512) n = 512;
    for (int i = t; i < n; i += 256) { su[i] = ui[base + i]; sI[i] = ii[base + i]; }
    __syncthreads();

    int sub = t & 7, grp = t >> 3;
    if (n == 512) {
#pragma unroll
        for (int pass = 0; pass < 8; ++pass) {
            int p = grp + pass * 64;
            int u0 = su[p],      i0 = sI[p];
            int u1 = su[p + 32], i1 = sI[p + 32];
            float4 a0 = *reinterpret_cast<const float4*>(&g_last[(size_t)u0 * DIM + sub * 4]);
            float4 b0 = *reinterpret_cast<const float4*>(&g_item_fus[(size_t)i0 * DIM + sub * 4]);
            float4 a1 = *reinterpret_cast<const float4*>(&g_last[(size_t)u1 * DIM + sub * 4]);
            float4 b1 = *reinterpret_cast<const float4*>(&g_item_fus[(size_t)i1 * DIM + sub * 4]);
            float d0 = a0.x * b0.x + a0.y * b0.y + a0.z * b0.z + a0.w * b0.w;
            float d1 = a1.x * b1.x + a1.y * b1.y + a1.z * b1.z + a1.w * b1.w;
#pragma unroll
            for (int o = 4; o; o >>= 1) {
                d0 += __shfl_down_sync(0xffffffffu, d0, o, 8);
                d1 += __shfl_down_sync(0xffffffffu, d1, o, 8);
            }
            if (sub == 0) {
                int gp0 = base + p, gp1 = base + p + 32;
                out[gp0] = d0;
                out[NPAIRS + gp0] = 1.f / (1.f + expf(-d0));
                out[gp1] = d1;
                out[NPAIRS + gp1] = 1.f / (1.f + expf(-d1));
            }
        }
    } else {
        for (int p = grp; p < n; p += 32) {
            int u  = su[p];
            int it = sI[p];
            float4 a = *reinterpret_cast<const float4*>(&g_last[(size_t)u * DIM + sub * 4]);
            float4 b = *reinterpret_cast<const float4*>(&g_item_fus[(size_t)it * DIM + sub * 4]);
            float d = a.x * b.x + a.y * b.y + a.z * b.z + a.w * b.w;
#pragma unroll
            for (int o = 4; o; o >>= 1) d += __shfl_down_sync(0xffffffffu, d, o, 8);
            if (sub == 0) {
                int gp = base + p;
                if (gp < out_size) out[gp] = d;
                if (NPAIRS + gp < out_size) out[NPAIRS + gp] = 1.f / (1.f + expf(-d));
            }
        }
    }
}

// ---------------- launch: wsplit first, then fork ----------------
extern "C" void kernel_launch(void* const* d_in, const int* in_sizes, int n_in,
                              void* d_out, int out_size) {
    const float* uf    = (const float*)d_in[0];
    const float* itf   = (const float*)d_in[1];
    const float* uemb  = (const float*)d_in[2];
    const float* iemb  = (const float*)d_in[3];
    const float* wr_w  = (const float*)d_in[4];
    const float* wr_b  = (const float*)d_in[5];
    const int*   srows = (const int*)d_in[6];
    const int*   scols = (const int*)d_in[7];
    const float* svals = (const float*)d_in[8];
    const int*   urows = (const int*)d_in[9];
    const int*   ucols = (const int*)d_in[10];
    const float* uvals = (const float*)d_in[11];
    const int*   uidx  = (const int*)d_in[12];
    const int*   iidx  = (const int*)d_in[13];
    float* out = (float*)d_out;

    static cudaStream_t sA = 0, sB = 0;
    static cudaEvent_t  eFork = 0, eInit = 0, eA = 0, eB = 0;
    if (sA == 0) {
        cudaStreamCreateWithFlags(&sA, cudaStreamNonBlocking);
        cudaStreamCreateWithFlags(&sB, cudaStreamNonBlocking);
        cudaEventCreateWithFlags(&eFork, cudaEventDisableTiming);
        cudaEventCreateWithFlags(&eInit, cudaEventDisableTiming);
        cudaEventCreateWithFlags(&eA, cudaEventDisableTiming);
        cudaEventCreateWithFlags(&eB, cudaEventDisableTiming);
    }

    // W split on origin stream (needed by both gemms), then fork
    k_wsplit<<<(NFEATS * DIM + 255) / 256, 256>>>(wr_w);
    cudaEventRecord(eFork, 0);
    cudaStreamWaitEvent(sA, eFork, 0);
    cudaStreamWaitEvent(sB, eFork, 0);

    // stream A (slack): init + colsum, then item chain -> UI SpMM
    k_init<<<(NUSERS * DIM / 4 + 255) / 256, 256, 0, sA>>>();
    k_colsum<<<1, 256, 0, sA>>>(wr_w);
    cudaEventRecord(eInit, sA);
    k_gemm_tc<<<(NITEMS + 63) / 64, 128, 0, sA>>>(itf, NITEMS, 2, 1);
    k_scal<<<1, 1, 0, sA>>>(2, (double)NITEMS * NFEATS, 0);
    k_epi<<<(NITEMS * DIM + 255) / 256, 256, 0, sA>>>(wr_b, NITEMS * DIM, 2, 6, 1);
    k_scal<<<1, 1, 0, sA>>>(6, (double)(NITEMS * DIM), 1);
    k_fusion<<<(NITEMS * DIM + 255) / 256, 256, 0, sA>>>(iemb, NITEMS * DIM, 6, 1);
    k_spmm<<<EUI / SPMM_EB, 256, 0, sA>>>(urows, ucols, uvals, 0, 0);

    // stream B (critical): user chain -> soc1 -> soc2
    k_gemm_tc<<<(NUSERS + 63) / 64, 128, 0, sB>>>(uf, NUSERS, 0, 0);
    k_scal<<<1, 1, 0, sB>>>(0, (double)NUSERS * NFEATS, 0);
    cudaStreamWaitEvent(sB, eInit, 0);          // colsum (epi) + zeroed bufs (spmm)
    k_epi<<<(NUSERS * DIM + 255) / 256, 256, 0, sB>>>(wr_b, NUSERS * DIM, 0, 4, 0);
    k_scal<<<1, 1, 0, sB>>>(4, (double)(NUSERS * DIM), 1);
    k_fusion<<<(NUSERS * DIM + 255) / 256, 256, 0, sB>>>(uemb, NUSERS * DIM, 4, 0);
    k_spmm<<<ESOC / SPMM_EB, 256, 0, sB>>>(srows, scols, svals, 1, 1);
    k_spmm<<<ESOC / SPMM_EB, 256, 0, sB>>>(srows, scols, svals, 2, 0);

    // join
    cudaEventRecord(eA, sA);
    cudaEventRecord(eB, sB);
    cudaStreamWaitEvent(0, eA, 0);
    cudaStreamWaitEvent(0, eB, 0);
    k_pred<<<(NPAIRS + 511) / 512, 256>>>(uidx, iidx, out, out_size);
}